// round 2
// baseline (speedup 1.0000x reference)
#include <cuda_runtime.h>
#include <math.h>

// Problem constants (fixed by the dataset)
#define NN    50000
#define EE    800000
#define HD    128
#define ND    64
#define ED    16
#define NL    3
#define LN_EPS 1e-5f

// ---------------- device scratch (static; no allocation allowed) ----------------
__device__ float g_h   [NN * HD];        // 25.6 MB  current node features
__device__ float g_aggr[NN * HD];        // 25.6 MB  aggregation buffer, reused as hl
__device__ float g_z   [NN * 2 * HD];    // 51.2 MB  MLP hidden
__device__ float g_sl  [NL * HD];        // per-layer self-loop embedded vector
__device__ float g_bnsum[2 * HD];        // batchnorm sums / sumsq

// ============================================================================
// node_embed: h = relu(LN(x @ node_W^T + node_b))
// block = 128 threads (thread t owns output feature t), grid-stride over nodes
// ============================================================================
__global__ __launch_bounds__(128) void node_embed_kernel(
    const float* __restrict__ x, const float* __restrict__ W,
    const float* __restrict__ b, const float* __restrict__ g,
    const float* __restrict__ bt, float* __restrict__ h, int n)
{
    __shared__ float sWT[ND * HD];   // [k][j] transposed for conflict-free reads
    __shared__ float sx[ND];
    __shared__ float red[8];

    const int t = threadIdx.x;
    for (int idx = t; idx < ND * HD; idx += 128) {
        int j = idx / ND, k = idx % ND;
        sWT[k * HD + j] = W[idx];
    }
    const float bj = b[t], gj = g[t], btj = bt[t];
    __syncthreads();

    for (int nd = blockIdx.x; nd < n; nd += gridDim.x) {
        if (t < ND) sx[t] = x[nd * ND + t];
        __syncthreads();
        float acc = bj;
        #pragma unroll
        for (int k = 0; k < ND; ++k)
            acc += sx[k] * sWT[k * HD + t];
        // LayerNorm over the 128 features (block reduction)
        float s1 = acc, s2 = acc * acc;
        #pragma unroll
        for (int o = 16; o; o >>= 1) {
            s1 += __shfl_xor_sync(0xFFFFFFFFu, s1, o);
            s2 += __shfl_xor_sync(0xFFFFFFFFu, s2, o);
        }
        const int w = t >> 5, lane = t & 31;
        if (lane == 0) { red[w] = s1; red[4 + w] = s2; }
        __syncthreads();
        s1 = red[0] + red[1] + red[2] + red[3];
        s2 = red[4] + red[5] + red[6] + red[7];
        const float mean = s1 * (1.0f / HD);
        const float var  = s2 * (1.0f / HD) - mean * mean;
        const float out  = fmaxf((acc - mean) * rsqrtf(var + LN_EPS) * gj + btj, 0.0f);
        h[nd * HD + t] = out;
        __syncthreads();   // protect sx / red before next iteration
    }
}

// ============================================================================
// sl_embed: per-layer self-loop edge embedding (single H-vector per layer)
// grid = NL blocks of 128 threads
// ============================================================================
__global__ __launch_bounds__(128) void sl_embed_kernel(
    const float* __restrict__ sl_attr, const float* __restrict__ W,
    const float* __restrict__ b, const float* __restrict__ g,
    const float* __restrict__ bt, float* __restrict__ slv)
{
    __shared__ float sa[ED];
    __shared__ float red[8];
    const int l = blockIdx.x, t = threadIdx.x;
    if (t < ED) sa[t] = sl_attr[l * ED + t];
    __syncthreads();
    float acc = b[l * HD + t];
    #pragma unroll
    for (int k = 0; k < ED; ++k)
        acc += sa[k] * W[(l * HD + t) * ED + k];
    float s1 = acc, s2 = acc * acc;
    #pragma unroll
    for (int o = 16; o; o >>= 1) {
        s1 += __shfl_xor_sync(0xFFFFFFFFu, s1, o);
        s2 += __shfl_xor_sync(0xFFFFFFFFu, s2, o);
    }
    const int w = t >> 5, lane = t & 31;
    if (lane == 0) { red[w] = s1; red[4 + w] = s2; }
    __syncthreads();
    s1 = red[0] + red[1] + red[2] + red[3];
    s2 = red[4] + red[5] + red[6] + red[7];
    const float mean = s1 * (1.0f / HD);
    const float var  = s2 * (1.0f / HD) - mean * mean;
    slv[l * HD + t] = fmaxf((acc - mean) * rsqrtf(var + LN_EPS) * g[l * HD + t] + bt[l * HD + t], 0.0f);
}

// ============================================================================
// init_aggr: aggr = h + sl_vec  (self-loop contribution), also zero bn sums
// ============================================================================
__global__ void init_aggr_kernel(const float* __restrict__ h,
                                 const float* __restrict__ sl,
                                 float* __restrict__ aggr,
                                 float* __restrict__ bnsum, int n)
{
    const int idx = blockIdx.x * blockDim.x + threadIdx.x;
    if (blockIdx.x == 0 && threadIdx.x < 2 * HD) bnsum[threadIdx.x] = 0.0f;
    const int total4 = n * (HD / 4);
    if (idx >= total4) return;
    const int jg = idx & (HD / 4 - 1);
    float4 hv = reinterpret_cast<const float4*>(h)[idx];
    float4 sv = reinterpret_cast<const float4*>(sl)[jg];
    float4 o; o.x = hv.x + sv.x; o.y = hv.y + sv.y; o.z = hv.z + sv.z; o.w = hv.w + sv.w;
    reinterpret_cast<float4*>(aggr)[idx] = o;
}

// ============================================================================
// edge_scatter: per edge e: ea = relu(LN(edge_attr @ W^T + b));
//               aggr[dst] += h[src] + ea        (warp per edge, lane owns 4 feats)
// ============================================================================
__global__ __launch_bounds__(256) void edge_scatter_kernel(
    const int* __restrict__ src, const int* __restrict__ dst,
    const float* __restrict__ ea,
    const float* __restrict__ W,   // [HD][ED]
    const float* __restrict__ b, const float* __restrict__ g,
    const float* __restrict__ bt,
    const float* __restrict__ h, float* __restrict__ aggr, int e_cnt)
{
    const int lane = threadIdx.x & 31;
    int warp  = (blockIdx.x * blockDim.x + threadIdx.x) >> 5;
    const int nwarp = (gridDim.x * blockDim.x) >> 5;

    // lane owns features j = 4*lane .. 4*lane+3; keep the 4 W rows in registers
    float4 wr[4][4];
    #pragma unroll
    for (int r = 0; r < 4; ++r)
        #pragma unroll
        for (int kg = 0; kg < 4; ++kg)
            wr[r][kg] = reinterpret_cast<const float4*>(W)[(lane * 4 + r) * 4 + kg];
    const float4 bias = reinterpret_cast<const float4*>(b )[lane];
    const float4 gv   = reinterpret_cast<const float4*>(g )[lane];
    const float4 btv  = reinterpret_cast<const float4*>(bt)[lane];

    for (int e = warp; e < e_cnt; e += nwarp) {
        const int s = src[e];
        const int d = dst[e];
        // 16 edge-attr floats: lane (lane&3) holds float4 group (lane&3)
        const float4 eav = reinterpret_cast<const float4*>(ea)[e * 4 + (lane & 3)];

        float acc[4] = { bias.x, bias.y, bias.z, bias.w };
        #pragma unroll
        for (int kg = 0; kg < 4; ++kg) {
            float4 v;
            v.x = __shfl_sync(0xFFFFFFFFu, eav.x, kg);
            v.y = __shfl_sync(0xFFFFFFFFu, eav.y, kg);
            v.z = __shfl_sync(0xFFFFFFFFu, eav.z, kg);
            v.w = __shfl_sync(0xFFFFFFFFu, eav.w, kg);
            #pragma unroll
            for (int r = 0; r < 4; ++r) {
                acc[r] += wr[r][kg].x * v.x + wr[r][kg].y * v.y
                        + wr[r][kg].z * v.z + wr[r][kg].w * v.w;
            }
        }
        // LayerNorm over 128 values spread across the warp (4 per lane)
        float s1 = acc[0] + acc[1] + acc[2] + acc[3];
        float s2 = acc[0]*acc[0] + acc[1]*acc[1] + acc[2]*acc[2] + acc[3]*acc[3];
        #pragma unroll
        for (int o = 16; o; o >>= 1) {
            s1 += __shfl_xor_sync(0xFFFFFFFFu, s1, o);
            s2 += __shfl_xor_sync(0xFFFFFFFFu, s2, o);
        }
        const float mean = s1 * (1.0f / HD);
        const float var  = s2 * (1.0f / HD) - mean * mean;
        const float inv  = rsqrtf(var + LN_EPS);

        const float4 hv = reinterpret_cast<const float4*>(h)[s * (HD / 4) + lane];
        float m0 = fmaxf((acc[0] - mean) * inv * gv.x + btv.x, 0.0f) + hv.x;
        float m1 = fmaxf((acc[1] - mean) * inv * gv.y + btv.y, 0.0f) + hv.y;
        float m2 = fmaxf((acc[2] - mean) * inv * gv.z + btv.z, 0.0f) + hv.z;
        float m3 = fmaxf((acc[3] - mean) * inv * gv.w + btv.w, 0.0f) + hv.w;

        float* dp = aggr + d * HD + lane * 4;
        asm volatile("red.global.add.v4.f32 [%0], {%1, %2, %3, %4};"
                     :: "l"(dp), "f"(m0), "f"(m1), "f"(m2), "f"(m3) : "memory");
    }
}

// ============================================================================
// GEMM: C[N,P] = act(A[N,K] @ W[P,K]^T + bias)     ACT: 0=none, 1=exact GELU
// Full W transposed in smem, 8-accumulator register blocking, 128-node tiles
// ============================================================================
template <int K, int P, int ACT>
__global__ __launch_bounds__(256) void gemm_kernel(
    const float* __restrict__ A, const float* __restrict__ W,
    const float* __restrict__ bias, float* __restrict__ C, int n)
{
    extern __shared__ float smem[];
    float* sW = smem;             // K*P floats, layout [k][j]
    float* sA = smem + K * P;     // K*NC floats, layout [k][node]
    constexpr int NC = 2048 / P;  // nodes per inner tile (8 or 16)

    const int t    = threadIdx.x;
    const int j    = t % P;
    const int half = t / P;       // which 8-node subgroup this thread handles

    for (int idx = t; idx < K * P; idx += 256) {
        const int jj = idx / K, kk = idx % K;
        sW[kk * P + jj] = W[idx];
    }
    const int n0 = blockIdx.x * 128;
    const float bj = bias[j];

    for (int it = 0; it < 128 / NC; ++it) {
        const int nb = n0 + it * NC;
        __syncthreads();
        for (int idx = t; idx < K * NC; idx += 256) {
            const int nn = idx / K, kk = idx % K;
            const int node = nb + nn;
            sA[kk * NC + nn] = (node < n) ? A[node * K + kk] : 0.0f;
        }
        __syncthreads();

        float acc[8];
        #pragma unroll
        for (int i = 0; i < 8; ++i) acc[i] = 0.0f;

        #pragma unroll 8
        for (int k = 0; k < K; ++k) {
            const float w = sW[k * P + j];
            const float4 a0 = *reinterpret_cast<const float4*>(&sA[k * NC + half * 8]);
            const float4 a1 = *reinterpret_cast<const float4*>(&sA[k * NC + half * 8 + 4]);
            acc[0] += w * a0.x; acc[1] += w * a0.y; acc[2] += w * a0.z; acc[3] += w * a0.w;
            acc[4] += w * a1.x; acc[5] += w * a1.y; acc[6] += w * a1.z; acc[7] += w * a1.w;
        }
        #pragma unroll
        for (int i = 0; i < 8; ++i) {
            const int node = nb + half * 8 + i;
            if (node < n) {
                float v = acc[i] + bj;
                if (ACT == 1)
                    v = 0.5f * v * (1.0f + erff(v * 0.70710678118654752f));
                C[node * P + j] = v;
            }
        }
    }
}

// ============================================================================
// BatchNorm: reduce (sum, sumsq) per feature, then normalize (+optional relu)
// ============================================================================
__global__ __launch_bounds__(128) void bn_reduce_kernel(
    const float* __restrict__ hl, float* __restrict__ bnsum, int n)
{
    const int j = threadIdx.x;
    float s = 0.0f, s2 = 0.0f;
    for (int nd = blockIdx.x; nd < n; nd += gridDim.x) {
        const float v = hl[nd * HD + j];
        s += v; s2 += v * v;
    }
    atomicAdd(&bnsum[j], s);
    atomicAdd(&bnsum[HD + j], s2);
}

__global__ void bn_apply_kernel(
    const float* __restrict__ hl, const float* __restrict__ bnsum,
    const float* __restrict__ g, const float* __restrict__ b,
    float* __restrict__ out, int n, int do_relu)
{
    const int idx = blockIdx.x * blockDim.x + threadIdx.x;
    const int total4 = n * (HD / 4);
    if (idx >= total4) return;
    const int j0 = (idx & (HD / 4 - 1)) * 4;
    const float inv_n = 1.0f / (float)n;
    float4 v = reinterpret_cast<const float4*>(hl)[idx];
    float4 o;
    {
        const float mean = bnsum[j0 + 0] * inv_n;
        const float var  = bnsum[HD + j0 + 0] * inv_n - mean * mean;
        o.x = (v.x - mean) * rsqrtf(var + LN_EPS) * g[j0 + 0] + b[j0 + 0];
    }
    {
        const float mean = bnsum[j0 + 1] * inv_n;
        const float var  = bnsum[HD + j0 + 1] * inv_n - mean * mean;
        o.y = (v.y - mean) * rsqrtf(var + LN_EPS) * g[j0 + 1] + b[j0 + 1];
    }
    {
        const float mean = bnsum[j0 + 2] * inv_n;
        const float var  = bnsum[HD + j0 + 2] * inv_n - mean * mean;
        o.z = (v.z - mean) * rsqrtf(var + LN_EPS) * g[j0 + 2] + b[j0 + 2];
    }
    {
        const float mean = bnsum[j0 + 3] * inv_n;
        const float var  = bnsum[HD + j0 + 3] * inv_n - mean * mean;
        o.w = (v.w - mean) * rsqrtf(var + LN_EPS) * g[j0 + 3] + b[j0 + 3];
    }
    if (do_relu) {
        o.x = fmaxf(o.x, 0.0f); o.y = fmaxf(o.y, 0.0f);
        o.z = fmaxf(o.z, 0.0f); o.w = fmaxf(o.w, 0.0f);
    }
    reinterpret_cast<float4*>(out)[idx] = o;
}

// ============================================================================
// launch
// ============================================================================
extern "C" void kernel_launch(void* const* d_in, const int* in_sizes, int n_in,
                              void* d_out, int out_size)
{
    const float* x         = (const float*)d_in[0];
    const int*   ei        = (const int*)  d_in[1];
    const float* edge_attr = (const float*)d_in[2];
    const float* node_W    = (const float*)d_in[3];
    const float* node_b    = (const float*)d_in[4];
    const float* node_ln_g = (const float*)d_in[5];
    const float* node_ln_b = (const float*)d_in[6];
    const float* edge_W    = (const float*)d_in[7];
    const float* edge_b    = (const float*)d_in[8];
    const float* edge_ln_g = (const float*)d_in[9];
    const float* edge_ln_b = (const float*)d_in[10];
    const float* sl_attr   = (const float*)d_in[11];
    const float* mlp_W1    = (const float*)d_in[12];
    const float* mlp_b1    = (const float*)d_in[13];
    const float* mlp_W2    = (const float*)d_in[14];
    const float* mlp_b2    = (const float*)d_in[15];
    const float* bn_g      = (const float*)d_in[16];
    const float* bn_b      = (const float*)d_in[17];

    const int n = in_sizes[0] / ND;      // 50000
    const int e = in_sizes[2] / ED;      // 800000
    const int* src = ei;
    const int* dst = ei + e;

    float *hbuf, *abuf, *zbuf, *slbuf, *bnbuf;
    cudaGetSymbolAddress((void**)&hbuf,  g_h);
    cudaGetSymbolAddress((void**)&abuf,  g_aggr);
    cudaGetSymbolAddress((void**)&zbuf,  g_z);
    cudaGetSymbolAddress((void**)&slbuf, g_sl);
    cudaGetSymbolAddress((void**)&bnbuf, g_bnsum);

    const int SMEM1 = (128 * 256 + 128 * 8)  * 4;   // 135168
    const int SMEM2 = (256 * 128 + 256 * 16) * 4;   // 147456
    cudaFuncSetAttribute((const void*)gemm_kernel<128, 256, 1>,
                         cudaFuncAttributeMaxDynamicSharedMemorySize, SMEM1);
    cudaFuncSetAttribute((const void*)gemm_kernel<256, 128, 0>,
                         cudaFuncAttributeMaxDynamicSharedMemorySize, SMEM2);

    const int grid_elem = (n * (HD / 4) + 255) / 256;    // float4-grain kernels
    const int grid_gemm = (n + 127) / 128;

    node_embed_kernel<<<512, 128>>>(x, node_W, node_b, node_ln_g, node_ln_b, hbuf, n);
    sl_embed_kernel<<<NL, 128>>>(sl_attr, edge_W, edge_b, edge_ln_g, edge_ln_b, slbuf);

    for (int l = 0; l < NL; ++l) {
        init_aggr_kernel<<<grid_elem, 256>>>(hbuf, slbuf + l * HD, abuf, bnbuf, n);
        edge_scatter_kernel<<<1024, 256>>>(src, dst, edge_attr,
                                           edge_W + l * HD * ED, edge_b + l * HD,
                                           edge_ln_g + l * HD, edge_ln_b + l * HD,
                                           hbuf, abuf, e);
        gemm_kernel<128, 256, 1><<<grid_gemm, 256, SMEM1>>>(
            abuf, mlp_W1 + l * 2 * HD * HD, mlp_b1 + l * 2 * HD, zbuf, n);
        // hl written back into abuf (aggr no longer needed)
        gemm_kernel<256, 128, 0><<<grid_gemm, 256, SMEM2>>>(
            zbuf, mlp_W2 + l * HD * 2 * HD, mlp_b2 + l * HD, abuf, n);
        bn_reduce_kernel<<<512, 128>>>(abuf, bnbuf, n);
        float* outp = (l == NL - 1) ? (float*)d_out : hbuf;
        bn_apply_kernel<<<grid_elem, 256>>>(abuf, bnbuf, bn_g + l * HD, bn_b + l * HD,
                                            outp, n, (l != NL - 1) ? 1 : 0);
    }
}

// round 3
// speedup vs baseline: 1.1387x; 1.1387x over previous
#include <cuda_runtime.h>
#include <math.h>

// Problem constants (fixed by the dataset)
#define NN    50000
#define EE    800000
#define HD    128
#define ND    64
#define ED    16
#define NL    3
#define LN_EPS 1e-5f
#define CHUNK 100000          // edges per ea-embed chunk (CHUNK*HD floats == g_z size)

typedef unsigned long long ull;

// ---------------- device scratch (static; no allocation allowed) ----------------
__device__ float g_h   [NN * HD];        // 25.6 MB  current node features
__device__ float g_aggr[NN * HD];        // 25.6 MB  aggregation buffer, reused as hl
__device__ float g_z   [NN * 2 * HD];    // 51.2 MB  MLP hidden / ea-embed chunk buffer
__device__ float g_sl  [NL * HD];        // per-layer self-loop embedded vector
__device__ float g_bnsum[2 * HD];        // batchnorm sums / sumsq

// ---------------- f32x2 helpers (Blackwell packed fp32 FMA) ----------------
__device__ __forceinline__ void ffma2(ull& d, ull a, ull b) {
    asm("fma.rn.f32x2 %0, %1, %2, %0;" : "+l"(d) : "l"(a), "l"(b));
}
__device__ __forceinline__ ull packf2(float x) {
    ull r;
    asm("mov.b64 %0, {%1, %1};" : "=l"(r) : "f"(x));
    return r;
}
__device__ __forceinline__ float2 unpackf2(ull v) {
    float lo, hi;
    asm("mov.b64 {%0, %1}, %2;" : "=f"(lo), "=f"(hi) : "l"(v));
    return make_float2(lo, hi);
}
__device__ __forceinline__ float gelu_exact(float v) {
    return 0.5f * v * (1.0f + erff(v * 0.70710678118654752f));
}

// ============================================================================
// node_embed: h = relu(LN(x @ node_W^T + node_b))
// ============================================================================
__global__ __launch_bounds__(128) void node_embed_kernel(
    const float* __restrict__ x, const float* __restrict__ W,
    const float* __restrict__ b, const float* __restrict__ g,
    const float* __restrict__ bt, float* __restrict__ h, int n)
{
    __shared__ float sWT[ND * HD];   // [k][j]
    __shared__ float sx[ND];
    __shared__ float red[8];

    const int t = threadIdx.x;
    for (int idx = t; idx < ND * HD; idx += 128) {
        int j = idx / ND, k = idx % ND;
        sWT[k * HD + j] = W[idx];
    }
    const float bj = b[t], gj = g[t], btj = bt[t];
    __syncthreads();

    for (int nd = blockIdx.x; nd < n; nd += gridDim.x) {
        if (t < ND) sx[t] = x[nd * ND + t];
        __syncthreads();
        float acc = bj;
        #pragma unroll
        for (int k = 0; k < ND; ++k)
            acc += sx[k] * sWT[k * HD + t];
        float s1 = acc, s2 = acc * acc;
        #pragma unroll
        for (int o = 16; o; o >>= 1) {
            s1 += __shfl_xor_sync(0xFFFFFFFFu, s1, o);
            s2 += __shfl_xor_sync(0xFFFFFFFFu, s2, o);
        }
        const int w = t >> 5, lane = t & 31;
        if (lane == 0) { red[w] = s1; red[4 + w] = s2; }
        __syncthreads();
        s1 = red[0] + red[1] + red[2] + red[3];
        s2 = red[4] + red[5] + red[6] + red[7];
        const float mean = s1 * (1.0f / HD);
        const float var  = s2 * (1.0f / HD) - mean * mean;
        h[nd * HD + t] = fmaxf((acc - mean) * rsqrtf(var + LN_EPS) * gj + btj, 0.0f);
        __syncthreads();
    }
}

// ============================================================================
// sl_embed: per-layer self-loop edge embedding
// ============================================================================
__global__ __launch_bounds__(128) void sl_embed_kernel(
    const float* __restrict__ sl_attr, const float* __restrict__ W,
    const float* __restrict__ b, const float* __restrict__ g,
    const float* __restrict__ bt, float* __restrict__ slv)
{
    __shared__ float sa[ED];
    __shared__ float red[8];
    const int l = blockIdx.x, t = threadIdx.x;
    if (t < ED) sa[t] = sl_attr[l * ED + t];
    __syncthreads();
    float acc = b[l * HD + t];
    #pragma unroll
    for (int k = 0; k < ED; ++k)
        acc += sa[k] * W[(l * HD + t) * ED + k];
    float s1 = acc, s2 = acc * acc;
    #pragma unroll
    for (int o = 16; o; o >>= 1) {
        s1 += __shfl_xor_sync(0xFFFFFFFFu, s1, o);
        s2 += __shfl_xor_sync(0xFFFFFFFFu, s2, o);
    }
    const int w = t >> 5, lane = t & 31;
    if (lane == 0) { red[w] = s1; red[4 + w] = s2; }
    __syncthreads();
    s1 = red[0] + red[1] + red[2] + red[3];
    s2 = red[4] + red[5] + red[6] + red[7];
    const float mean = s1 * (1.0f / HD);
    const float var  = s2 * (1.0f / HD) - mean * mean;
    slv[l * HD + t] = fmaxf((acc - mean) * rsqrtf(var + LN_EPS) * g[l * HD + t] + bt[l * HD + t], 0.0f);
}

// ============================================================================
// init_aggr: aggr = h + sl_vec; also zero bn sums
// ============================================================================
__global__ void init_aggr_kernel(const float* __restrict__ h,
                                 const float* __restrict__ sl,
                                 float* __restrict__ aggr,
                                 float* __restrict__ bnsum, int n)
{
    const int idx = blockIdx.x * blockDim.x + threadIdx.x;
    if (blockIdx.x == 0 && threadIdx.x < 2 * HD) bnsum[threadIdx.x] = 0.0f;
    const int total4 = n * (HD / 4);
    if (idx >= total4) return;
    const int jg = idx & (HD / 4 - 1);
    float4 hv = reinterpret_cast<const float4*>(h)[idx];
    float4 sv = reinterpret_cast<const float4*>(sl)[jg];
    float4 o; o.x = hv.x + sv.x; o.y = hv.y + sv.y; o.z = hv.z + sv.z; o.w = hv.w + sv.w;
    reinterpret_cast<float4*>(aggr)[idx] = o;
}

// ============================================================================
// edge_embed: out[e][j] = relu(LN(edge_attr[e] @ W^T + b))  for a chunk of edges
// block = 128 threads (thread j owns feature j, W row in registers),
// 64-edge tiles staged through shared memory, LN via per-edge warp reductions.
// ============================================================================
#define ETILE 64
__global__ __launch_bounds__(128) void edge_embed_kernel(
    const float* __restrict__ attr, const float* __restrict__ W,
    const float* __restrict__ b, const float* __restrict__ g,
    const float* __restrict__ bt, float* __restrict__ out,
    int e0, int ecnt)
{
    __shared__ float sattr[ETILE * ED];      // 4 KB
    __shared__ float sy[ETILE * HD];         // 32 KB
    __shared__ float sstat[ETILE * 2];

    const int t = threadIdx.x;
    float wr[ED];
    #pragma unroll
    for (int k = 0; k < ED; ++k) wr[k] = W[t * ED + k];
    const float bj = b[t], gj = g[t], btj = bt[t];

    const int ntile = (ecnt + ETILE - 1) / ETILE;
    for (int tile = blockIdx.x; tile < ntile; tile += gridDim.x) {
        const int ebase = tile * ETILE;      // edge index within chunk
        __syncthreads();                      // protect sattr/sy/sstat reuse
        // stage edge_attr tile (ETILE*ED floats = 256 float4)
        for (int i = t; i < ETILE * (ED / 4); i += 128) {
            const int ee = i >> 2;
            float4 v = (ebase + ee < ecnt)
                ? reinterpret_cast<const float4*>(attr)[(e0 + ebase + ee) * (ED / 4) + (i & 3)]
                : make_float4(0.f, 0.f, 0.f, 0.f);
            reinterpret_cast<float4*>(sattr)[i] = v;
        }
        __syncthreads();
        // matvec: y[e][j]
        #pragma unroll 4
        for (int e2 = 0; e2 < ETILE; ++e2) {
            const float4* ap = reinterpret_cast<const float4*>(&sattr[e2 * ED]);
            const float4 a0 = ap[0], a1 = ap[1], a2 = ap[2], a3 = ap[3];
            float y = bj;
            y += wr[0]  * a0.x + wr[1]  * a0.y + wr[2]  * a0.z + wr[3]  * a0.w;
            y += wr[4]  * a1.x + wr[5]  * a1.y + wr[6]  * a1.z + wr[7]  * a1.w;
            y += wr[8]  * a2.x + wr[9]  * a2.y + wr[10] * a2.z + wr[11] * a2.w;
            y += wr[12] * a3.x + wr[13] * a3.y + wr[14] * a3.z + wr[15] * a3.w;
            sy[e2 * HD + t] = y;
        }
        __syncthreads();
        // per-edge LN stats: 4 warps x 16 edges
        {
            const int w = t >> 5, lane = t & 31;
            for (int e2 = w; e2 < ETILE; e2 += 4) {
                const float4 v = reinterpret_cast<const float4*>(&sy[e2 * HD])[lane];
                float s1 = v.x + v.y + v.z + v.w;
                float s2 = v.x * v.x + v.y * v.y + v.z * v.z + v.w * v.w;
                #pragma unroll
                for (int o = 16; o; o >>= 1) {
                    s1 += __shfl_xor_sync(0xFFFFFFFFu, s1, o);
                    s2 += __shfl_xor_sync(0xFFFFFFFFu, s2, o);
                }
                if (lane == 0) {
                    const float mean = s1 * (1.0f / HD);
                    const float var  = s2 * (1.0f / HD) - mean * mean;
                    sstat[e2 * 2]     = mean;
                    sstat[e2 * 2 + 1] = rsqrtf(var + LN_EPS);
                }
            }
        }
        __syncthreads();
        // normalize + relu + store
        #pragma unroll 4
        for (int e2 = 0; e2 < ETILE; ++e2) {
            const int eg = ebase + e2;
            if (eg < ecnt) {
                const float mean = sstat[e2 * 2];
                const float inv  = sstat[e2 * 2 + 1];
                const float y = sy[e2 * HD + t];
                out[(size_t)eg * HD + t] = fmaxf((y - mean) * inv * gj + btj, 0.0f);
            }
        }
    }
}

// ============================================================================
// scatter: warp per edge: aggr[dst] += h[src] + ea_emb[e]   (lane owns 4 feats)
// tiny register footprint -> high occupancy to hide gather + RED latency
// ============================================================================
__global__ __launch_bounds__(256) void scatter_kernel(
    const int* __restrict__ src, const int* __restrict__ dst,
    const float* __restrict__ h, const float* __restrict__ eaemb,
    float* __restrict__ aggr, int e0, int ecnt)
{
    const int gt = blockIdx.x * 256 + threadIdx.x;
    const int e = gt >> 5;
    const int lane = gt & 31;
    if (e >= ecnt) return;
    const int s = __ldg(&src[e0 + e]);
    const int d = __ldg(&dst[e0 + e]);
    const float4 hv = reinterpret_cast<const float4*>(h)[s * (HD / 4) + lane];
    const float4 ev = reinterpret_cast<const float4*>(eaemb)[(size_t)e * (HD / 4) + lane];
    const float m0 = hv.x + ev.x, m1 = hv.y + ev.y, m2 = hv.z + ev.z, m3 = hv.w + ev.w;
    float* dp = aggr + d * HD + lane * 4;
    asm volatile("red.global.add.v4.f32 [%0], {%1, %2, %3, %4};"
                 :: "l"(dp), "f"(m0), "f"(m1), "f"(m2), "f"(m3) : "memory");
}

// ============================================================================
// GEMM (f32x2): C[:, fb:fb+128] = act(A[N,K] @ W[fb:fb+128,:K]^T + bias)
// Block: THREADS threads, 128-node x 128-feature tile, padded smem strides.
// Thread (j, q): feature j, node subgroup q (8 nodes as 4 f32x2 accumulators).
// ============================================================================
template <int K, int THREADS, int ACT>
__global__ __launch_bounds__(THREADS) void gemm_f2_kernel(
    const float* __restrict__ A, const float* __restrict__ W,
    const float* __restrict__ bias, float* __restrict__ C, int n, int Ptot)
{
    constexpr int NQ  = THREADS / 128;
    constexpr int NC  = NQ * 8;       // nodes per inner tile
    constexpr int NCP = NC + 2;       // padded (even -> 8B alignment kept)
    extern __shared__ float smem[];
    float* sW = smem;                 // [k][j]  stride 129 (conflict-free)
    float* sA = smem + K * 129;       // [k][node] stride NCP

    const int t = threadIdx.x;
    const int j = t & 127;
    const int q = t >> 7;
    const int fb = blockIdx.y * 128;

    for (int idx = t; idx < K * 128; idx += THREADS) {
        const int jj = idx / K, kk = idx % K;     // K is power of two
        sW[kk * 129 + jj] = W[(fb + jj) * K + kk];
    }
    const int n0 = blockIdx.x * 128;
    const float bj = bias[fb + j];

    for (int it = 0; it < 128 / NC; ++it) {
        const int nb = n0 + it * NC;
        __syncthreads();
        for (int idx = t; idx < K * NC; idx += THREADS) {
            const int nn = idx / K, kk = idx % K;
            const int node = nb + nn;
            sA[kk * NCP + nn] = (node < n) ? A[node * K + kk] : 0.0f;
        }
        __syncthreads();

        ull acc0 = 0, acc1 = 0, acc2 = 0, acc3 = 0;   // (0.f,0.f) bit patterns
        #pragma unroll 8
        for (int k = 0; k < K; ++k) {
            const ull wp = packf2(sW[k * 129 + j]);
            const float* ab = &sA[k * NCP + q * 8];
            ffma2(acc0, *reinterpret_cast<const ull*>(ab + 0), wp);
            ffma2(acc1, *reinterpret_cast<const ull*>(ab + 2), wp);
            ffma2(acc2, *reinterpret_cast<const ull*>(ab + 4), wp);
            ffma2(acc3, *reinterpret_cast<const ull*>(ab + 6), wp);
        }

        const ull accs[4] = { acc0, acc1, acc2, acc3 };
        #pragma unroll
        for (int i = 0; i < 4; ++i) {
            const float2 v = unpackf2(accs[i]);
            const int node0 = nb + q * 8 + 2 * i;
            if (node0 < n) {
                float r = v.x + bj;
                if (ACT) r = gelu_exact(r);
                C[node0 * Ptot + fb + j] = r;
            }
            if (node0 + 1 < n) {
                float r = v.y + bj;
                if (ACT) r = gelu_exact(r);
                C[(node0 + 1) * Ptot + fb + j] = r;
            }
        }
    }
}

// ============================================================================
// BatchNorm
// ============================================================================
__global__ __launch_bounds__(128) void bn_reduce_kernel(
    const float* __restrict__ hl, float* __restrict__ bnsum, int n)
{
    const int j = threadIdx.x;
    float s = 0.0f, s2 = 0.0f;
    for (int nd = blockIdx.x; nd < n; nd += gridDim.x) {
        const float v = hl[nd * HD + j];
        s += v; s2 += v * v;
    }
    atomicAdd(&bnsum[j], s);
    atomicAdd(&bnsum[HD + j], s2);
}

__global__ void bn_apply_kernel(
    const float* __restrict__ hl, const float* __restrict__ bnsum,
    const float* __restrict__ g, const float* __restrict__ b,
    float* __restrict__ out, int n, int do_relu)
{
    const int idx = blockIdx.x * blockDim.x + threadIdx.x;
    const int total4 = n * (HD / 4);
    if (idx >= total4) return;
    const int j0 = (idx & (HD / 4 - 1)) * 4;
    const float inv_n = 1.0f / (float)n;
    float4 v = reinterpret_cast<const float4*>(hl)[idx];
    float4 o;
    {
        const float mean = bnsum[j0 + 0] * inv_n;
        const float var  = bnsum[HD + j0 + 0] * inv_n - mean * mean;
        o.x = (v.x - mean) * rsqrtf(var + LN_EPS) * g[j0 + 0] + b[j0 + 0];
    }
    {
        const float mean = bnsum[j0 + 1] * inv_n;
        const float var  = bnsum[HD + j0 + 1] * inv_n - mean * mean;
        o.y = (v.y - mean) * rsqrtf(var + LN_EPS) * g[j0 + 1] + b[j0 + 1];
    }
    {
        const float mean = bnsum[j0 + 2] * inv_n;
        const float var  = bnsum[HD + j0 + 2] * inv_n - mean * mean;
        o.z = (v.z - mean) * rsqrtf(var + LN_EPS) * g[j0 + 2] + b[j0 + 2];
    }
    {
        const float mean = bnsum[j0 + 3] * inv_n;
        const float var  = bnsum[HD + j0 + 3] * inv_n - mean * mean;
        o.w = (v.w - mean) * rsqrtf(var + LN_EPS) * g[j0 + 3] + b[j0 + 3];
    }
    if (do_relu) {
        o.x = fmaxf(o.x, 0.0f); o.y = fmaxf(o.y, 0.0f);
        o.z = fmaxf(o.z, 0.0f); o.w = fmaxf(o.w, 0.0f);
    }
    reinterpret_cast<float4*>(out)[idx] = o;
}

// ============================================================================
// launch
// ============================================================================
extern "C" void kernel_launch(void* const* d_in, const int* in_sizes, int n_in,
                              void* d_out, int out_size)
{
    const float* x         = (const float*)d_in[0];
    const int*   ei        = (const int*)  d_in[1];
    const float* edge_attr = (const float*)d_in[2];
    const float* node_W    = (const float*)d_in[3];
    const float* node_b    = (const float*)d_in[4];
    const float* node_ln_g = (const float*)d_in[5];
    const float* node_ln_b = (const float*)d_in[6];
    const float* edge_W    = (const float*)d_in[7];
    const float* edge_b    = (const float*)d_in[8];
    const float* edge_ln_g = (const float*)d_in[9];
    const float* edge_ln_b = (const float*)d_in[10];
    const float* sl_attr   = (const float*)d_in[11];
    const float* mlp_W1    = (const float*)d_in[12];
    const float* mlp_b1    = (const float*)d_in[13];
    const float* mlp_W2    = (const float*)d_in[14];
    const float* mlp_b2    = (const float*)d_in[15];
    const float* bn_g      = (const float*)d_in[16];
    const float* bn_b      = (const float*)d_in[17];

    const int n = in_sizes[0] / ND;      // 50000
    const int e = in_sizes[2] / ED;      // 800000
    const int* src = ei;
    const int* dst = ei + e;

    float *hbuf, *abuf, *zbuf, *slbuf, *bnbuf;
    cudaGetSymbolAddress((void**)&hbuf,  g_h);
    cudaGetSymbolAddress((void**)&abuf,  g_aggr);
    cudaGetSymbolAddress((void**)&zbuf,  g_z);
    cudaGetSymbolAddress((void**)&slbuf, g_sl);
    cudaGetSymbolAddress((void**)&bnbuf, g_bnsum);

    // GEMM1: K=128, 256 threads; GEMM2: K=256, 512 threads
    const int SMEM1 = (128 * 129 + 128 * 18) * 4;   // 75264
    const int SMEM2 = (256 * 129 + 256 * 34) * 4;   // 166912
    cudaFuncSetAttribute((const void*)gemm_f2_kernel<128, 256, 1>,
                         cudaFuncAttributeMaxDynamicSharedMemorySize, SMEM1);
    cudaFuncSetAttribute((const void*)gemm_f2_kernel<256, 512, 0>,
                         cudaFuncAttributeMaxDynamicSharedMemorySize, SMEM2);

    const int grid_elem = (n * (HD / 4) + 255) / 256;
    const int grid_gemm = (n + 127) / 128;

    node_embed_kernel<<<512, 128>>>(x, node_W, node_b, node_ln_g, node_ln_b, hbuf, n);
    sl_embed_kernel<<<NL, 128>>>(sl_attr, edge_W, edge_b, edge_ln_g, edge_ln_b, slbuf);

    for (int l = 0; l < NL; ++l) {
        init_aggr_kernel<<<grid_elem, 256>>>(hbuf, slbuf + l * HD, abuf, bnbuf, n);

        // edge message + scatter in L2-resident chunks (ea chunk lives in zbuf)
        for (int c = 0; c < e; c += CHUNK) {
            const int cnt = (e - c < CHUNK) ? (e - c) : CHUNK;
            edge_embed_kernel<<<888, 128>>>(edge_attr,
                                            edge_W + l * HD * ED, edge_b + l * HD,
                                            edge_ln_g + l * HD, edge_ln_b + l * HD,
                                            zbuf, c, cnt);
            const int sblocks = (cnt * 32 + 255) / 256;
            scatter_kernel<<<sblocks, 256>>>(src, dst, hbuf, zbuf, abuf, c, cnt);
        }

        gemm_f2_kernel<128, 256, 1><<<dim3(grid_gemm, 2), 256, SMEM1>>>(
            abuf, mlp_W1 + l * 2 * HD * HD, mlp_b1 + l * 2 * HD, zbuf, n, 2 * HD);
        gemm_f2_kernel<256, 512, 0><<<dim3(grid_gemm, 1), 512, SMEM2>>>(
            zbuf, mlp_W2 + l * HD * 2 * HD, mlp_b2 + l * HD, abuf, n, HD);

        bn_reduce_kernel<<<512, 128>>>(abuf, bnbuf, n);
        float* outp = (l == NL - 1) ? (float*)d_out : hbuf;
        bn_apply_kernel<<<grid_elem, 256>>>(abuf, bnbuf, bn_g + l * HD, bn_b + l * HD,
                                            outp, n, (l != NL - 1) ? 1 : 0);
    }
}